// round 17
// baseline (speedup 1.0000x reference)
#include <cuda_runtime.h>
#include <math.h>

#define BB 2
#define QQ 2048
#define FF 1538
#define CH 514          // faces per smem chunk (3 chunks cover 1538)
#define BLOCKS_PER_BATCH 512

__device__ float g_res[BB * QQ];
__device__ float g_partial[BB];
__device__ unsigned int g_cnt[BB] = {0, 0};
__device__ unsigned int g_cnt2 = 0;

// ---------------------------------------------------------------------------
// fast helpers
// ---------------------------------------------------------------------------
__device__ __forceinline__ float sqrt_approx(float x) {
    float r; asm("sqrt.approx.f32 %0, %1;" : "=f"(r) : "f"(x)); return r;
}
__device__ __forceinline__ float rcp_approx(float x) {
    float r; asm("rcp.approx.f32 %0, %1;" : "=f"(r) : "f"(x)); return r;
}

// atan2 via quadrant folding + degree-11 odd minimax poly (|err| ~ 3e-6)
__device__ __forceinline__ float fast_atan2(float y, float x) {
    float ax = fabsf(x), ay = fabsf(y);
    float mx = fmaxf(ax, ay), mn = fminf(ax, ay);
    float t = mn * rcp_approx(mx);
    float s = t * t;
    float p =             -0.01172120f;
    p = fmaf(p, s,  0.05265332f);
    p = fmaf(p, s, -0.11643287f);
    p = fmaf(p, s,  0.19354346f);
    p = fmaf(p, s, -0.33262347f);
    p = fmaf(p, s,  0.99997726f);
    float r = p * t;
    if (ay > ax) r = 1.57079632679f - r;
    if (x < 0.0f) r = 3.14159265359f - r;
    return copysignf(r, y);
}

// one face (from smem float4s) against one query point -> solid-angle atan term
__device__ __forceinline__ float face_term(const float4 v0, const float4 v1,
                                           const float4 v2,
                                           float px, float py, float pz) {
    float ax = v0.x - px, ay = v0.y - py, az = v0.z - pz;
    float bx = v0.w - px, by = v1.x - py, bz = v1.y - pz;
    float cx = v1.z - px, cy = v1.w - py, cz = v2.x - pz;

    float na = sqrt_approx(fmaf(ax, ax, fmaf(ay, ay, az * az)));
    float nb = sqrt_approx(fmaf(bx, bx, fmaf(by, by, bz * bz)));
    float nc = sqrt_approx(fmaf(cx, cx, fmaf(cy, cy, cz * cz)));

    float crx = by * cz - bz * cy;
    float cry = bz * cx - bx * cz;
    float crz = bx * cy - by * cx;

    float num = fmaf(ax, crx, fmaf(ay, cry, az * crz));
    float d01 = fmaf(ax, bx, fmaf(ay, by, az * bz));
    float d12 = fmaf(bx, cx, fmaf(by, cy, bz * cz));
    float d02 = fmaf(ax, cx, fmaf(ay, cy, az * cz));

    float den = fmaf(na * nb, nc, fmaf(d01, nc, fmaf(d02, nb, d12 * na)));
    return fast_atan2(num, den);
}

// ---------------------------------------------------------------------------
// robust-select machinery (128-thread version)
// ---------------------------------------------------------------------------
__device__ __forceinline__ unsigned int fkey(float f) {
    unsigned int u = __float_as_uint(f);
    return (u & 0x80000000u) ? ~u : (u | 0x80000000u);
}
__device__ __forceinline__ float key_to_float(unsigned int k) {
    unsigned int bits = (k & 0x80000000u) ? (k ^ 0x80000000u) : ~k;
    return __uint_as_float(bits);
}

struct SelShared {
    unsigned int hist[256];
    unsigned int wtot[4];
    unsigned int bc[3];      // bin, new k, bin count / result value
    unsigned int cand[64];
    unsigned int ccnt;
};

struct RbSmem {
    float        rs[QQ];
    unsigned int keys[QQ];
    SelShared    ss;
    float        red[4];
};
struct WnSmem {
    float st[CH * 12];
    float sacc[8];
};
union SmemU {
    WnSmem wn;
    RbSmem rb;
};

// k-th smallest (0-indexed) of QQ keys; 128 threads.
__device__ unsigned int radix_select_128(const unsigned int* keys, SelShared* ss,
                                         int tid, int k) {
    int wid  = tid >> 5;     // 0..3
    int lane = tid & 31;
    unsigned int prefix = 0;

    for (int shift = 24; shift >= 0; shift -= 8) {
        ss->hist[tid] = 0;
        ss->hist[tid + 128] = 0;
        if (tid == 0) ss->ccnt = 0;
        __syncthreads();

        unsigned int hi = (shift == 24) ? 0u : (0xFFFFFFFFu << (shift + 8));
        #pragma unroll
        for (int i = tid; i < QQ; i += 128) {    // 16 iterations
            unsigned int u = keys[i];
            if ((u & hi) == prefix) atomicAdd(&ss->hist[(u >> shift) & 255u], 1u);
        }
        __syncthreads();

        // scan 256 bins: each thread owns 2 adjacent bins
        unsigned int c0 = ss->hist[2 * tid];
        unsigned int c1 = ss->hist[2 * tid + 1];
        unsigned int my = c0 + c1;
        unsigned int v  = my;
        #pragma unroll
        for (int o = 1; o < 32; o <<= 1) {
            unsigned int y = __shfl_up_sync(0xFFFFFFFFu, v, o);
            if (lane >= o) v += y;
        }
        if (lane == 31) ss->wtot[wid] = v;
        __syncthreads();
        if (tid < 4) {
            unsigned int t0 = ss->wtot[tid];
            unsigned int t  = t0;
            #pragma unroll
            for (int o = 1; o < 4; o <<= 1) {
                unsigned int y = __shfl_up_sync(0x0000000Fu, t, o);
                if (tid >= o) t += y;
            }
            ss->wtot[tid] = t - t0;    // exclusive warp offset
        }
        __syncthreads();

        unsigned int inc = v + ss->wtot[wid];
        unsigned int exc = inc - my;
        // bin 2*tid covers ranks [exc, exc+c0); bin 2*tid+1 covers [exc+c0, inc)
        if ((int)exc <= k && k < (int)(exc + c0)) {
            ss->bc[0] = 2u * tid;
            ss->bc[1] = (unsigned int)(k - (int)exc);
            ss->bc[2] = c0;
        }
        if ((int)(exc + c0) <= k && k < (int)inc) {
            ss->bc[0] = 2u * tid + 1u;
            ss->bc[1] = (unsigned int)(k - (int)(exc + c0));
            ss->bc[2] = c1;
        }
        __syncthreads();

        prefix |= (ss->bc[0] << shift);
        k = (int)ss->bc[1];
        unsigned int cnt = ss->bc[2];

        if (shift > 0 && cnt <= 64u) {
            unsigned int hi2 = 0xFFFFFFFFu << shift;
            #pragma unroll
            for (int i = tid; i < QQ; i += 128) {
                unsigned int u = keys[i];
                if ((u & hi2) == prefix) {
                    unsigned int p = atomicAdd(&ss->ccnt, 1u);
                    ss->cand[p] = u;
                }
            }
            __syncthreads();
            if (tid < (int)cnt) {
                unsigned int x = ss->cand[tid];
                int less = 0, eq = 0;
                for (int j = 0; j < (int)cnt; j++) {
                    unsigned int u = ss->cand[j];
                    less += (u < x);
                    eq   += (u == x);
                }
                if (less <= k && k < less + eq) ss->bc[2] = x;
            }
            __syncthreads();
            return ss->bc[2];
        }
        __syncthreads();
    }
    return prefix;
}

// full robust stage for one batch, 128 threads, smem overlay
__device__ void robust_128(RbSmem* rb, int b, int tid, float* out) {
    #pragma unroll
    for (int i = tid; i < QQ; i += 128) {
        float v = g_res[b * QQ + i];
        rb->rs[i]   = v;
        rb->keys[i] = fkey(v);
    }
    __syncthreads();

    float med = key_to_float(radix_select_128(rb->keys, &rb->ss, tid, (QQ - 1) / 2));
    __syncthreads();

    #pragma unroll
    for (int i = tid; i < QQ; i += 128)
        rb->keys[i] = fkey(fabsf(rb->rs[i] - med));
    __syncthreads();

    float mad = key_to_float(radix_select_128(rb->keys, &rb->ss, tid, (QQ - 1) / 2));

    float scale = (mad / 0.67449f) * 4.6851f;

    float sum = 0.0f;
    #pragma unroll
    for (int i = tid; i < QQ; i += 128) {
        float r  = rb->rs[i];
        float nr = r / scale;
        float t  = 1.0f - nr * nr;
        float w  = (nr >= 1.0f) ? 0.0f : t * t;
        sum += w * r * r;
    }

    #pragma unroll
    for (int o = 16; o > 0; o >>= 1)
        sum += __shfl_xor_sync(0xFFFFFFFFu, sum, o);
    if ((tid & 31) == 0) rb->red[tid >> 5] = sum;
    __syncthreads();

    if (tid == 0) {
        float s = rb->red[0] + rb->red[1] + rb->red[2] + rb->red[3];
        g_partial[b] = s;
        __threadfence();
        unsigned int p2 = atomicAdd(&g_cnt2, 1u);
        if (p2 == BB - 1) {
            out[0] = 0.5f * (g_partial[0] + g_partial[1]);
            g_cnt[0] = 0;       // reset for next graph replay
            g_cnt[1] = 0;
            g_cnt2   = 0;
        }
    }
}

// ---------------------------------------------------------------------------
// Fused kernel: winding numbers + residuals; last block per batch runs the
// robust stage in-place (smem overlaid). Single launch.
// ---------------------------------------------------------------------------
__global__ __launch_bounds__(128) void fused_kernel(const float* __restrict__ points,
                                                    const float* __restrict__ tris,
                                                    const float* __restrict__ occ,
                                                    float* __restrict__ out) {
    __shared__ SmemU sm;
    __shared__ int   s_role;

    int tid  = threadIdx.x;
    int warp = tid >> 5;          // 0..3
    int lane = tid & 31;
    int pair = warp >> 1;         // query pair 0/1 within block
    int half = warp & 1;          // face-stride half

    int qA = blockIdx.x * 4 + pair * 2;   // 1024 blocks * 4 queries = 4096
    int qB = qA + 1;
    int b  = qA >> 11;                    // batch (uniform per block)

    float pxA = points[qA * 3 + 0], pyA = points[qA * 3 + 1], pzA = points[qA * 3 + 2];
    float pxB = points[qB * 3 + 0], pyB = points[qB * 3 + 1], pzB = points[qB * 3 + 2];

    const float* tb = tris + (size_t)b * FF * 9;

    float accA = 0.0f, accB = 0.0f;
    for (int base = 0; base < FF; base += CH) {
        int nf = min(CH, FF - base);
        __syncthreads();
        for (int f = tid; f < nf; f += 128) {
            const float* src = tb + (size_t)(base + f) * 9;
            float* dst = &sm.wn.st[f * 12];
            #pragma unroll
            for (int c = 0; c < 9; c++) dst[c] = src[c];
        }
        __syncthreads();

        int f = half * 32 + lane;
        for (; f + 64 < nf; f += 128) {
            const float4* t4a = (const float4*)&sm.wn.st[f * 12];
            float4 u0 = t4a[0], u1 = t4a[1], u2 = t4a[2];
            const float4* t4b = (const float4*)&sm.wn.st[(f + 64) * 12];
            float4 w0 = t4b[0], w1 = t4b[1], w2 = t4b[2];

            accA += face_term(u0, u1, u2, pxA, pyA, pzA);
            accB += face_term(u0, u1, u2, pxB, pyB, pzB);
            accA += face_term(w0, w1, w2, pxA, pyA, pzA);
            accB += face_term(w0, w1, w2, pxB, pyB, pzB);
        }
        for (; f < nf; f += 64) {
            const float4* t4 = (const float4*)&sm.wn.st[f * 12];
            float4 v0 = t4[0], v1 = t4[1], v2 = t4[2];
            accA += face_term(v0, v1, v2, pxA, pyA, pzA);
            accB += face_term(v0, v1, v2, pxB, pyB, pzB);
        }
    }

    #pragma unroll
    for (int o = 16; o > 0; o >>= 1) {
        accA += __shfl_xor_sync(0xFFFFFFFFu, accA, o);
        accB += __shfl_xor_sync(0xFFFFFFFFu, accB, o);
    }

    if (lane == 0) {
        sm.wn.sacc[warp * 2 + 0] = accA;
        sm.wn.sacc[warp * 2 + 1] = accB;
    }
    __syncthreads();

    if (tid < 4) {  // tid = local query index 0..3
        int p    = tid >> 1;
        int qloc = tid & 1;
        float tot = sm.wn.sacc[(p * 2 + 0) * 2 + qloc]
                  + sm.wn.sacc[(p * 2 + 1) * 2 + qloc];
        int q = blockIdx.x * 4 + tid;
        float wn = tot * 0.15915494309189535f;   // (2*atan2 sum)/(4*pi)
        g_res[q] = wn - occ[q];
    }
    __syncthreads();

    // completion counting: last block of each batch becomes the robust worker
    if (tid == 0) {
        __threadfence();                              // release residuals
        unsigned int prev = atomicAdd(&g_cnt[b], 1u);
        s_role = (prev == BLOCKS_PER_BATCH - 1) ? 1 : 0;
    }
    __syncthreads();
    if (!s_role) return;

    __threadfence();   // acquire: all residuals of this batch now visible
    robust_128(&sm.rb, b, tid, out);
}

extern "C" void kernel_launch(void* const* d_in, const int* in_sizes, int n_in,
                              void* d_out, int out_size) {
    const float* points = (const float*)d_in[0];  // (B,Q,3)
    const float* tris   = (const float*)d_in[1];  // (B,F,3,3)
    const float* occ    = (const float*)d_in[2];  // (B,Q)
    float* out = (float*)d_out;

    fused_kernel<<<(BB * QQ) / 4, 128>>>(points, tris, occ, out);
}